// round 7
// baseline (speedup 1.0000x reference)
#include <cuda_runtime.h>

// ---------------------------------------------------------------------------
// PhotonicLayer: out[b,n] = Re[(x @ U^T)[b,n] * exp(i*KERR*|.|^2)]  (float32)
// K1: build U — ping-pong scan (no STS->LDS aliasing), 1-FMA carry chain.
// K2: complex GEMM via packed fma.rn.f32x2 (halves issue pressure).
// ---------------------------------------------------------------------------

#define SIZE 64
#define NPH 2016
#define LOSS_AMP 0.9942600740f      // 10^(-0.05/20)
#define KERR 2.6e-17f               // NONLINEAR_COEFF * 1000
#define BB 128
#define XPITCH 129
#define UPITCH 66
#define OPITCH 65

typedef unsigned long long u64t;

#define FFMA2(acc, a, b) \
    asm("fma.rn.f32x2 %0, %1, %2, %0;" : "+l"(acc) : "l"(a), "l"(b))
#define PACK2(d, lo, hi) \
    asm("mov.b64 %0, {%1, %2};" : "=l"(d) : "f"(lo), "f"(hi))
#define UNPACK2(lo, hi, v) \
    asm("mov.b64 {%0, %1}, %2;" : "=f"(lo), "=f"(hi) : "l"(v))

__device__ float2 g_W[SIZE * SIZE]; // W[n*64+m] = U[n][m]

// one Reck layer: read src, write dst (distinct arrays -> loads hoistable)
__device__ __forceinline__ void do_layer(
    int i, int kbase,
    const float2 (*__restrict__ src)[SIZE],
    float2 (*__restrict__ dst)[SIZE],
    const float* __restrict__ cs, const float* __restrict__ sn, int t)
{
    float ar = src[0][t].x, ai = src[0][t].y;
    int k = kbase;
    #pragma unroll 4
    for (int j = 0; j < i; ++j, ++k) {
        const float cc = cs[k], ss = sn[k];
        const float2 b = src[j + 1][t];
        // independent pre-terms (no carry dep), then 1 FMA on the carry
        const float pr  =  cc * b.x;      // for nbr
        const float pi  =  cc * b.y;      // for nbi
        const float qr  = -ss * b.y;      // for nar
        const float qi  =  ss * b.x;      // for nai
        const float nar = fmaf(cc, ar, qr);
        const float nai = fmaf(cc, ai, qi);
        const float nbr = fmaf(-ss, ai, pr);
        const float nbi = fmaf( ss, ar, pi);
        dst[j][t] = make_float2(nar, nai);
        ar = nbr; ai = nbi;
    }
    dst[i][t] = make_float2(ar, ai);
    // untouched rows carry over
    #pragma unroll 4
    for (int r = i + 1; r < SIZE; ++r)
        dst[r][t] = src[r][t];
}

// ---------------------------- build kernel --------------------------------
__global__ void build_u_kernel(const float* __restrict__ phases, int nph) {
    extern __shared__ char bsm[];
    float2 (*Sa)[SIZE] = (float2(*)[SIZE])bsm;              // 32 KB
    float2 (*Sb)[SIZE] = (float2(*)[SIZE])(bsm + 32768);    // 32 KB
    float* cs = (float*)(bsm + 65536);                      // 8064 B
    float* sn = cs + NPH;                                   // 8064 B

    const int t = threadIdx.x;          // column 0..63
    const int pmax = (nph > 0) ? (nph - 1) : 0;

    for (int k = t; k < NPH; k += SIZE) {
        const int kk = (k < pmax) ? k : pmax;
        float sv, cv;
        sincosf(phases[kk], &sv, &cv);
        cs[k] = LOSS_AMP * cv;
        sn[k] = LOSS_AMP * sv;
    }
    for (int r = 0; r < SIZE; ++r)
        Sa[r][t] = make_float2(r == t ? 1.0f : 0.0f, 0.0f);
    __syncthreads();

    // layers 1..63; odd layer: Sa->Sb, even layer: Sb->Sa. 63 is odd -> Sb.
    for (int i = 1; i < SIZE; i += 2) {
        do_layer(i,     (i * (i - 1)) / 2,       Sa, Sb, cs, sn, t);
        if (i + 1 < SIZE)
            do_layer(i + 1, ((i + 1) * i) / 2,   Sb, Sa, cs, sn, t);
    }
    __syncthreads();

    for (int n = 0; n < SIZE; ++n)
        g_W[n * SIZE + t] = Sb[n][t];
}

// ----------------------------- GEMM kernel --------------------------------
// 256 threads; tile 128 batches x 64 outputs; packed f32x2 over (n, n+1).
__global__ __launch_bounds__(256, 2)
void photonic_gemm_kernel(const float* __restrict__ xr_g,
                          const float* __restrict__ xi_g,
                          float* __restrict__ out,
                          long long xsz, long long out_elems, int B) {
    extern __shared__ char smem[];
    float* sur = (float*)smem;                         // 64*66*4 = 16896 B
    float* sui = (float*)(smem + 16896);               // 16896 B
    float* sxr = (float*)(smem + 33792);               // 64*129*4 = 33024 B
    float* sxi = (float*)(smem + 33792 + 33024);       // 33024 B
    float* sout = (float*)(smem + 33792);              // reuse: 128*65*4 B

    const int tid  = threadIdx.x;
    const int lane = tid & 31;
    const int warp = tid >> 5;

    const long long b0 = (long long)blockIdx.x * BB;
    if (b0 >= B) return;

    // stage U into re/im planes, transposed to [m][n] with pitch 66
    for (int p = tid; p < SIZE * SIZE; p += 256) {
        const int n = p >> 6, m = p & 63;
        const float2 w = g_W[p];
        sur[m * UPITCH + n] = w.x;
        sui[m * UPITCH + n] = w.y;
    }

    // stage x transposed: sx[m][b]
    const long long base = b0 * SIZE;
    const long long xmax = xsz - 1;
    for (int p = tid; p < BB * SIZE; p += 256) {
        const int bb = p >> 6, m = p & 63;
        long long gi = base + p;
        if (gi > xmax) gi = xmax;
        sxr[m * XPITCH + bb] = xr_g[gi];
        sxi[m * XPITCH + bb] = xi_g[gi];
    }
    __syncthreads();

    // packed accumulators: [n-pair k=0..3][batch j=0..3], lanes = (n, n+1)
    u64t accr[4][4], acci[4][4];
    #pragma unroll
    for (int kk = 0; kk < 4; ++kk)
        #pragma unroll
        for (int j = 0; j < 4; ++j) { accr[kk][j] = 0ull; acci[kk][j] = 0ull; }

    const int nbase = warp * 8;

    #pragma unroll 2
    for (int m = 0; m < SIZE; ++m) {
        u64t uxp[4], uyp[4];
        #pragma unroll
        for (int kk = 0; kk < 4; ++kk) {
            uxp[kk] = *(const u64t*)&sur[m * UPITCH + nbase + 2 * kk];
            uyp[kk] = *(const u64t*)&sui[m * UPITCH + nbase + 2 * kk];
        }
        u64t xrd[4], xid[4], nxid[4];
        #pragma unroll
        for (int j = 0; j < 4; ++j) {
            const float xr = sxr[m * XPITCH + lane + 32 * j];
            const float xi = sxi[m * XPITCH + lane + 32 * j];
            const float nxi = -xi;
            PACK2(xrd[j], xr, xr);
            PACK2(xid[j], xi, xi);
            PACK2(nxid[j], nxi, nxi);
        }
        #pragma unroll
        for (int kk = 0; kk < 4; ++kk)
            #pragma unroll
            for (int j = 0; j < 4; ++j) {
                FFMA2(accr[kk][j], xrd[j],  uxp[kk]);
                FFMA2(accr[kk][j], nxid[j], uyp[kk]);
                FFMA2(acci[kk][j], xrd[j],  uyp[kk]);
                FFMA2(acci[kk][j], xid[j],  uxp[kk]);
            }
    }
    __syncthreads();   // x consumed; reuse shared for output staging

    // Kerr phase (ph ~ 1e-16): cos=1, sin=ph exactly in fp32 -> re - im*ph
    #pragma unroll
    for (int kk = 0; kk < 4; ++kk) {
        const int n = nbase + 2 * kk;
        #pragma unroll
        for (int j = 0; j < 4; ++j) {
            const int bidx = lane + 32 * j;
            float r0, r1, i0, i1;
            UNPACK2(r0, r1, accr[kk][j]);
            UNPACK2(i0, i1, acci[kk][j]);
            const float ph0 = KERR * fmaf(r0, r0, i0 * i0);
            const float ph1 = KERR * fmaf(r1, r1, i1 * i1);
            sout[bidx * OPITCH + n]     = fmaf(-i0, ph0, r0);
            sout[bidx * OPITCH + n + 1] = fmaf(-i1, ph1, r1);
        }
    }
    __syncthreads();

    // coalesced float store, guarded by out element count
    float* op = out + base;
    for (int q = tid; q < BB * SIZE; q += 256) {
        if (base + q < out_elems)
            op[q] = sout[(q >> 6) * OPITCH + (q & 63)];
    }
}

// ------------------------------- launch ------------------------------------
extern "C" void kernel_launch(void* const* d_in, const int* in_sizes, int n_in,
                              void* d_out, int out_size) {
    if (n_in < 3) return;

    // phases = the input with the smallest element count (2016 vs B*64)
    int ph_idx = 0;
    for (int i = 1; i < 3; ++i)
        if (in_sizes[i] < in_sizes[ph_idx]) ph_idx = i;

    const float* xr = nullptr;
    const float* xi = nullptr;
    long long xsz = 0;
    for (int i = 0; i < 3; ++i) {
        if (i == ph_idx) continue;
        if (!xr) { xr = (const float*)d_in[i]; xsz = in_sizes[i]; }
        else     { xi = (const float*)d_in[i]; }
    }
    const float* phases = (const float*)d_in[ph_idx];
    const int nph = in_sizes[ph_idx];

    const int B = (int)(xsz / SIZE);
    const int nblocks = (B + BB - 1) / BB;

    const int build_smem = 65536 + 2 * NPH * 4;            // 81,664 B
    cudaFuncSetAttribute(build_u_kernel,
                         cudaFuncAttributeMaxDynamicSharedMemorySize,
                         build_smem);

    const int smem_bytes = 33792 + 2 * SIZE * XPITCH * 4;  // 99,840 B
    cudaFuncSetAttribute(photonic_gemm_kernel,
                         cudaFuncAttributeMaxDynamicSharedMemorySize,
                         smem_bytes);

    build_u_kernel<<<1, SIZE, build_smem>>>(phases, nph);
    photonic_gemm_kernel<<<nblocks, 256, smem_bytes>>>(
        xr, xi, (float*)d_out, xsz, (long long)out_size, B);
}

// round 8
// speedup vs baseline: 1.0139x; 1.0139x over previous
#include <cuda_runtime.h>

// ---------------------------------------------------------------------------
// PhotonicLayer: out[b,n] = Re[(x @ U^T)[b,n] * exp(i*KERR*|.|^2)]  (float32)
// K1: build U — WAVEFRONT-parallel mesh scan (T = 2i+j), 512 threads.
// K2: complex GEMM, packed f32x2, 64-batch tiles, 3 blocks/SM.
// ---------------------------------------------------------------------------

#define SIZE 64
#define NPH 2016
#define LOSS_AMP 0.9942600740f      // 10^(-0.05/20)
#define KERR 2.6e-17f               // NONLINEAR_COEFF * 1000
#define BB 64
#define XPITCH 65                   // odd -> conflict-free x staging
#define UPITCH 66                   // even -> aligned LDS.64 u-pairs
#define OPITCH 65
#define BT 512                      // build kernel threads

typedef unsigned long long u64t;

#define FFMA2(acc, a, b) \
    asm("fma.rn.f32x2 %0, %1, %2, %0;" : "+l"(acc) : "l"(a), "l"(b))
#define PACK2(d, lo, hi) \
    asm("mov.b64 %0, {%1, %2};" : "=l"(d) : "f"(lo), "f"(hi))
#define UNPACK2(lo, hi, v) \
    asm("mov.b64 {%0, %1}, %2;" : "=f"(lo), "=f"(hi) : "l"(v))

__device__ float2 g_W[SIZE * SIZE]; // W[n*64+m] = U[n][m]

// ---------------------------- build kernel --------------------------------
// Wavefront schedule: rotation (i,j) (layer i=1..63, pos j=0..i-1, rows j,j+1)
// executes at T = 2i + j. Deps (i,j-1)@T-1, (i-1,j+1)@T-1, (i-1,j)@T-2 all
// earlier; same-T rotations touch disjoint row pairs (j differs by >=2).
__global__ __launch_bounds__(BT)
void build_u_kernel(const float* __restrict__ phases, int nph) {
    __shared__ float2 S[SIZE][SIZE];    // 32 KB, in-place state [row][col]
    __shared__ float cs[NPH];
    __shared__ float sn[NPH];

    const int tid  = threadIdx.x;
    const int lane = tid & 31;
    const int warp = tid >> 5;
    const int pmax = (nph > 0) ? (nph - 1) : 0;

    for (int k = tid; k < NPH; k += BT) {
        const int kk = (k < pmax) ? k : pmax;
        float sv, cv;
        sincosf(phases[kk], &sv, &cv);
        cs[k] = LOSS_AMP * cv;
        sn[k] = LOSS_AMP * sv;
    }
    for (int p = tid; p < SIZE * SIZE; p += BT) {
        const int r = p >> 6, c = p & 63;
        S[r][c] = make_float2(r == c ? 1.0f : 0.0f, 0.0f);
    }
    __syncthreads();

    // wavefronts w = 2..188 (w = 2i + j)
    for (int w = 2; w <= 188; ++w) {
        int i_min = (w + 3) / 3;              // ceil((w+1)/3)
        if (i_min < 1) i_min = 1;
        int i_max = w >> 1;
        if (i_max > 63) i_max = 63;
        const int cnt = i_max - i_min + 1;    // may be <= 0 (empty wavefront)

        for (int idx = warp; idx < cnt; idx += 16) {
            const int i = i_min + idx;
            const int j = w - 2 * i;
            const int k = ((i * (i - 1)) >> 1) + j;
            const float cc = cs[k], ss = sn[k];
            #pragma unroll
            for (int h = 0; h < 2; ++h) {     // 2 columns per lane
                const int c = lane + 32 * h;
                const float2 a = S[j][c];
                const float2 b = S[j + 1][c];
                const float nar = fmaf(cc, a.x, -(ss * b.y));
                const float nai = fmaf(cc, a.y,   ss * b.x);
                const float nbr = fmaf(cc, b.x, -(ss * a.y));
                const float nbi = fmaf(cc, b.y,   ss * a.x);
                S[j][c]     = make_float2(nar, nai);
                S[j + 1][c] = make_float2(nbr, nbi);
            }
        }
        __syncthreads();
    }

    for (int p = tid; p < SIZE * SIZE; p += BT)
        g_W[p] = S[p >> 6][p & 63];
}

// ----------------------------- GEMM kernel --------------------------------
// 256 threads; tile 64 batches x 64 outputs; packed f32x2 over (n, n+1).
// 3 blocks/SM (smem 67 KB, regs < 84) -> 24 warps/SM.
__global__ __launch_bounds__(256, 3)
void photonic_gemm_kernel(const float* __restrict__ xr_g,
                          const float* __restrict__ xi_g,
                          float* __restrict__ out,
                          long long xsz, long long out_elems, int B) {
    extern __shared__ char smem[];
    float* sur = (float*)smem;                         // 64*66*4 = 16896 B
    float* sui = (float*)(smem + 16896);               // 16896 B
    float* sxr = (float*)(smem + 33792);               // 64*65*4 = 16640 B
    float* sxi = (float*)(smem + 33792 + 16640);       // 16640 B
    float* sout = (float*)(smem + 33792);              // reuse: 64*65*4 B

    const int tid  = threadIdx.x;
    const int lane = tid & 31;
    const int warp = tid >> 5;

    const long long b0 = (long long)blockIdx.x * BB;
    if (b0 >= B) return;

    // stage U into re/im planes, transposed to [m][n] with pitch 66
    for (int p = tid; p < SIZE * SIZE; p += 256) {
        const int n = p >> 6, m = p & 63;
        const float2 w = g_W[p];
        sur[m * UPITCH + n] = w.x;
        sui[m * UPITCH + n] = w.y;
    }

    // stage x transposed: sx[m][b], b in [0,64)
    const long long base = b0 * SIZE;
    const long long xmax = xsz - 1;
    for (int p = tid; p < BB * SIZE; p += 256) {
        const int bb = p >> 6, m = p & 63;
        long long gi = base + p;
        if (gi > xmax) gi = xmax;
        sxr[m * XPITCH + bb] = xr_g[gi];
        sxi[m * XPITCH + bb] = xi_g[gi];
    }
    __syncthreads();

    // packed accumulators: [n-pair kk=0..3][batch j=0..1]
    u64t accr[4][2], acci[4][2];
    #pragma unroll
    for (int kk = 0; kk < 4; ++kk)
        #pragma unroll
        for (int j = 0; j < 2; ++j) { accr[kk][j] = 0ull; acci[kk][j] = 0ull; }

    const int nbase = warp * 8;

    #pragma unroll 2
    for (int m = 0; m < SIZE; ++m) {
        u64t uxp[4], uyp[4];
        #pragma unroll
        for (int kk = 0; kk < 4; ++kk) {
            uxp[kk] = *(const u64t*)&sur[m * UPITCH + nbase + 2 * kk];
            uyp[kk] = *(const u64t*)&sui[m * UPITCH + nbase + 2 * kk];
        }
        u64t xrd[2], xid[2], nxid[2];
        #pragma unroll
        for (int j = 0; j < 2; ++j) {
            const float xr = sxr[m * XPITCH + lane + 32 * j];
            const float xi = sxi[m * XPITCH + lane + 32 * j];
            const float nxi = -xi;
            PACK2(xrd[j], xr, xr);
            PACK2(xid[j], xi, xi);
            PACK2(nxid[j], nxi, nxi);
        }
        #pragma unroll
        for (int kk = 0; kk < 4; ++kk)
            #pragma unroll
            for (int j = 0; j < 2; ++j) {
                FFMA2(accr[kk][j], xrd[j],  uxp[kk]);
                FFMA2(accr[kk][j], nxid[j], uyp[kk]);
                FFMA2(acci[kk][j], xrd[j],  uyp[kk]);
                FFMA2(acci[kk][j], xid[j],  uxp[kk]);
            }
    }
    __syncthreads();   // x consumed; reuse shared for output staging

    // Kerr phase (ph ~ 1e-16): cos=1, sin=ph exactly in fp32 -> re - im*ph
    #pragma unroll
    for (int kk = 0; kk < 4; ++kk) {
        const int n = nbase + 2 * kk;
        #pragma unroll
        for (int j = 0; j < 2; ++j) {
            const int bidx = lane + 32 * j;
            float r0, r1, i0, i1;
            UNPACK2(r0, r1, accr[kk][j]);
            UNPACK2(i0, i1, acci[kk][j]);
            const float ph0 = KERR * fmaf(r0, r0, i0 * i0);
            const float ph1 = KERR * fmaf(r1, r1, i1 * i1);
            sout[bidx * OPITCH + n]     = fmaf(-i0, ph0, r0);
            sout[bidx * OPITCH + n + 1] = fmaf(-i1, ph1, r1);
        }
    }
    __syncthreads();

    // coalesced float store, guarded by out element count
    float* op = out + base;
    for (int q = tid; q < BB * SIZE; q += 256) {
        if (base + q < out_elems)
            op[q] = sout[(q >> 6) * OPITCH + (q & 63)];
    }
}

// ------------------------------- launch ------------------------------------
extern "C" void kernel_launch(void* const* d_in, const int* in_sizes, int n_in,
                              void* d_out, int out_size) {
    if (n_in < 3) return;

    // phases = the input with the smallest element count (2016 vs B*64)
    int ph_idx = 0;
    for (int i = 1; i < 3; ++i)
        if (in_sizes[i] < in_sizes[ph_idx]) ph_idx = i;

    const float* xr = nullptr;
    const float* xi = nullptr;
    long long xsz = 0;
    for (int i = 0; i < 3; ++i) {
        if (i == ph_idx) continue;
        if (!xr) { xr = (const float*)d_in[i]; xsz = in_sizes[i]; }
        else     { xi = (const float*)d_in[i]; }
    }
    const float* phases = (const float*)d_in[ph_idx];
    const int nph = in_sizes[ph_idx];

    const int B = (int)(xsz / SIZE);
    const int nblocks = (B + BB - 1) / BB;

    const int smem_bytes = 33792 + 2 * SIZE * XPITCH * 4;  // 67,072 B
    cudaFuncSetAttribute(photonic_gemm_kernel,
                         cudaFuncAttributeMaxDynamicSharedMemorySize,
                         smem_bytes);

    build_u_kernel<<<1, BT>>>(phases, nph);
    photonic_gemm_kernel<<<nblocks, 256, smem_bytes>>>(
        xr, xi, (float*)d_out, xsz, (long long)out_size, B);
}

// round 9
// speedup vs baseline: 1.5884x; 1.5666x over previous
#include <cuda_runtime.h>

// ---------------------------------------------------------------------------
// PhotonicLayer via TF32 tensor cores (mma.sync.m16n8k8).
// Complex GEMM recast as real GEMM: X=[xr|xi] (Bx128), W=[[Ur,-Ui],[Ui,Ur]]
// (128x128), out' = X @ W^T -> [out_re | out_im]; Kerr epilogue on recombine.
// K1: wavefront-parallel mesh build (T=2i+j) + write tf32-rounded W.
// K2: tensor-core GEMM, 128-batch tiles, fragments loaded by formula.
// ---------------------------------------------------------------------------

#define SIZE 64
#define NPH 2016
#define LOSS_AMP 0.9942600740f      // 10^(-0.05/20)
#define KERR 2.6e-17f               // NONLINEAR_COEFF * 1000
#define BT 512                      // build kernel threads
#define XP 132                      // X smem pitch: (132*r+c)%32=(4r+c)%32

__device__ float g_Wexp[128 * 128]; // W[n'][k'] tf32-rounded, row-major

// ---------------------------- build kernel --------------------------------
// Wavefront schedule: rotation (i,j) at T = 2i+j; same-T rotations touch
// disjoint row pairs -> in-place with one barrier per wavefront.
__global__ __launch_bounds__(BT)
void build_u_kernel(const float* __restrict__ phases, int nph) {
    __shared__ float2 S[SIZE][SIZE];    // [row][col] = U
    __shared__ float cs[NPH];
    __shared__ float sn[NPH];

    const int tid  = threadIdx.x;
    const int lane = tid & 31;
    const int warp = tid >> 5;
    const int pmax = (nph > 0) ? (nph - 1) : 0;

    for (int k = tid; k < NPH; k += BT) {
        const int kk = (k < pmax) ? k : pmax;
        float sv, cv;
        sincosf(phases[kk], &sv, &cv);
        cs[k] = LOSS_AMP * cv;
        sn[k] = LOSS_AMP * sv;
    }
    for (int p = tid; p < SIZE * SIZE; p += BT) {
        const int r = p >> 6, c = p & 63;
        S[r][c] = make_float2(r == c ? 1.0f : 0.0f, 0.0f);
    }
    __syncthreads();

    for (int w = 2; w <= 188; ++w) {
        int i_min = (w + 3) / 3;
        if (i_min < 1) i_min = 1;
        int i_max = w >> 1;
        if (i_max > 63) i_max = 63;
        const int cnt = i_max - i_min + 1;

        for (int idx = warp; idx < cnt; idx += 16) {
            const int i = i_min + idx;
            const int j = w - 2 * i;
            const int k = ((i * (i - 1)) >> 1) + j;
            const float cc = cs[k], ss = sn[k];
            #pragma unroll
            for (int h = 0; h < 2; ++h) {
                const int c = lane + 32 * h;
                const float2 a = S[j][c];
                const float2 b = S[j + 1][c];
                const float nar = fmaf(cc, a.x, -(ss * b.y));
                const float nai = fmaf(cc, a.y,   ss * b.x);
                const float nbr = fmaf(cc, b.x, -(ss * a.y));
                const float nbi = fmaf(cc, b.y,   ss * a.x);
                S[j][c]     = make_float2(nar, nai);
                S[j + 1][c] = make_float2(nbr, nbi);
            }
        }
        __syncthreads();
    }

    // write expanded W[n'][k'] tf32-rounded:
    //  n'<64: [ Ur | -Ui ] ;  n'>=64: [ Ui | Ur ]
    for (int p = tid; p < 128 * 128; p += BT) {
        const int n = p >> 7, k = p & 127;
        const float2 u = S[n & 63][k & 63];
        float v;
        if (n < 64) v = (k < 64) ? u.x : -u.y;
        else        v = (k < 64) ? u.y :  u.x;
        unsigned tv;
        asm("cvt.rna.tf32.f32 %0, %1;" : "=r"(tv) : "f"(v));
        g_Wexp[p] = __uint_as_float(tv);
    }
}

// ----------------------------- GEMM kernel --------------------------------
// 256 threads (8 warps: warpM 0..1 x warpN 0..3). Tile: 128 b x 128 n', K=128.
// Per warp: 4 m16-tiles x 4 n8-tiles, 16 k8-steps.
__global__ __launch_bounds__(256, 2)
void photonic_mma_kernel(const float* __restrict__ xr_g,
                         const float* __restrict__ xi_g,
                         float* __restrict__ out,
                         long long xsz, long long out_elems, int B) {
    extern __shared__ char smem[];
    float* sx = (float*)smem;                 // [128][132] f32; reused as sout
    unsigned* sxu = (unsigned*)smem;

    const int tid  = threadIdx.x;
    const int lane = tid & 31;
    const int warp = tid >> 5;
    const int g = lane >> 2;                  // groupID 0..7
    const int t = lane & 3;                   // threadID in group 0..3
    const int warpM = warp >> 2;              // 0..1
    const int warpN = warp & 3;               // 0..3

    const long long b0 = (long long)blockIdx.x * 128;
    if (b0 >= B) return;
    const long long base = b0 * SIZE;
    const long long xmax = xsz - 1;

    // ---- stage X = [xr | xi], tf32-rounded, [b][k] pitch 132 ----
    for (int p = tid; p < 128 * 64; p += 256) {
        const int bb = p >> 6, k = p & 63;
        long long gi = base + p;
        if (gi > xmax) gi = xmax;
        const float vr = xr_g[gi];
        const float vi = xi_g[gi];
        unsigned r_, i_;
        asm("cvt.rna.tf32.f32 %0, %1;" : "=r"(r_) : "f"(vr));
        asm("cvt.rna.tf32.f32 %0, %1;" : "=r"(i_) : "f"(vi));
        sxu[bb * XP + k]      = r_;
        sxu[bb * XP + k + 64] = i_;
    }
    __syncthreads();

    // ---- accumulators: [mt][nt][4] ----
    float c[4][4][4];
    #pragma unroll
    for (int mt = 0; mt < 4; ++mt)
        #pragma unroll
        for (int nt = 0; nt < 4; ++nt)
            #pragma unroll
            for (int q = 0; q < 4; ++q) c[mt][nt][q] = 0.0f;

    const unsigned* Wg = (const unsigned*)g_Wexp;

    #pragma unroll 4
    for (int ks = 0; ks < 16; ++ks) {
        // A fragments (bank-conflict-free: (4g+t) distinct)
        unsigned a[4][4];
        #pragma unroll
        for (int mt = 0; mt < 4; ++mt) {
            const int row = warpM * 64 + mt * 16 + g;
            const int col = ks * 8 + t;
            a[mt][0] = sxu[row * XP + col];
            a[mt][1] = sxu[(row + 8) * XP + col];
            a[mt][2] = sxu[row * XP + col + 4];
            a[mt][3] = sxu[(row + 8) * XP + col + 4];
        }
        // B fragments from global (64 KB, L1-resident)
        unsigned bf[4][2];
        #pragma unroll
        for (int nt = 0; nt < 4; ++nt) {
            const int n = warpN * 32 + nt * 8 + g;
            bf[nt][0] = __ldg(&Wg[n * 128 + ks * 8 + t]);
            bf[nt][1] = __ldg(&Wg[n * 128 + ks * 8 + t + 4]);
        }
        #pragma unroll
        for (int mt = 0; mt < 4; ++mt)
            #pragma unroll
            for (int nt = 0; nt < 4; ++nt)
                asm volatile(
                    "mma.sync.aligned.m16n8k8.row.col.f32.tf32.tf32.f32 "
                    "{%0,%1,%2,%3}, {%4,%5,%6,%7}, {%8,%9}, {%0,%1,%2,%3};"
                    : "+f"(c[mt][nt][0]), "+f"(c[mt][nt][1]),
                      "+f"(c[mt][nt][2]), "+f"(c[mt][nt][3])
                    : "r"(a[mt][0]), "r"(a[mt][1]), "r"(a[mt][2]), "r"(a[mt][3]),
                      "r"(bf[nt][0]), "r"(bf[nt][1]));
    }
    __syncthreads();   // X consumed; reuse smem as sout[128][132]

    // ---- write C fragments to smem: sout[b][n'] ----
    #pragma unroll
    for (int mt = 0; mt < 4; ++mt) {
        const int row = warpM * 64 + mt * 16 + g;
        #pragma unroll
        for (int nt = 0; nt < 4; ++nt) {
            const int col = warpN * 32 + nt * 8 + 2 * t;
            *(float2*)&sx[row * XP + col] =
                make_float2(c[mt][nt][0], c[mt][nt][1]);
            *(float2*)&sx[(row + 8) * XP + col] =
                make_float2(c[mt][nt][2], c[mt][nt][3]);
        }
    }
    __syncthreads();

    // ---- recombine re/im + Kerr, coalesced store ----
    for (int p = tid; p < 128 * 64; p += 256) {
        const int bb = p >> 6, n = p & 63;
        const float re = sx[bb * XP + n];
        const float im = sx[bb * XP + n + 64];
        const float ph = KERR * fmaf(re, re, im * im);
        if (base + p < out_elems)
            out[base + p] = fmaf(-im, ph, re);   // cos(ph)=1, sin(ph)=ph (fp32)
    }
}

// ------------------------------- launch ------------------------------------
extern "C" void kernel_launch(void* const* d_in, const int* in_sizes, int n_in,
                              void* d_out, int out_size) {
    if (n_in < 3) return;

    // phases = the input with the smallest element count (2016 vs B*64)
    int ph_idx = 0;
    for (int i = 1; i < 3; ++i)
        if (in_sizes[i] < in_sizes[ph_idx]) ph_idx = i;

    const float* xr = nullptr;
    const float* xi = nullptr;
    long long xsz = 0;
    for (int i = 0; i < 3; ++i) {
        if (i == ph_idx) continue;
        if (!xr) { xr = (const float*)d_in[i]; xsz = in_sizes[i]; }
        else     { xi = (const float*)d_in[i]; }
    }
    const float* phases = (const float*)d_in[ph_idx];
    const int nph = in_sizes[ph_idx];

    const int B = (int)(xsz / SIZE);
    const int nblocks = (B + 127) / 128;

    const int smem_bytes = 128 * XP * 4;   // 67,584 B
    cudaFuncSetAttribute(photonic_mma_kernel,
                         cudaFuncAttributeMaxDynamicSharedMemorySize,
                         smem_bytes);

    build_u_kernel<<<1, BT>>>(phases, nph);
    photonic_mma_kernel<<<nblocks, 256, smem_bytes>>>(
        xr, xi, (float*)d_out, xsz, (long long)out_size, B);
}

// round 10
// speedup vs baseline: 1.9337x; 1.2174x over previous
#include <cuda_runtime.h>

// ---------------------------------------------------------------------------
// PhotonicLayer via TF32 tensor cores (mma.sync.m16n8k8), fragment-packed.
// Real GEMM: X=[xr|xi] (Bx128), W=[[Ur,-Ui],[Ui,Ur]] (128x128), out'=X@W^T.
// A (X) staged in smem in fragment order -> LDS.128 per fragment.
// B (W) written by build kernel in fragment order -> coalesced LDG.64.
// ---------------------------------------------------------------------------

#define SIZE 64
#define NPH 2016
#define LOSS_AMP 0.9942600740f      // 10^(-0.05/20)
#define KERR 2.6e-17f               // NONLINEAR_COEFF * 1000
#define BT 1024                     // build kernel threads (32 warps)
#define SP 66                       // epilogue staging pitch (float2-aligned)

// W in fragment order: flat idx = (((n8t*16 + ks)*32 + lane)*2 + q)
__device__ unsigned g_Wfrag[16 * 16 * 32 * 2];   // 64 KB

// ---------------------------- build kernel --------------------------------
// Wavefront schedule: rotation (i,j) at T = 2i+j; same-T rotations touch
// disjoint row pairs -> in-place, one barrier per wavefront. 32 warps cover
// the widest wavefront (21 rotations) in a single pass.
__global__ __launch_bounds__(BT)
void build_u_kernel(const float* __restrict__ phases, int nph) {
    __shared__ float2 S[SIZE][SIZE];    // [row][col] = U
    __shared__ float cs[NPH];
    __shared__ float sn[NPH];

    const int tid  = threadIdx.x;
    const int lane = tid & 31;
    const int warp = tid >> 5;
    const int pmax = (nph > 0) ? (nph - 1) : 0;

    for (int k = tid; k < NPH; k += BT) {
        const int kk = (k < pmax) ? k : pmax;
        float sv, cv;
        sincosf(phases[kk], &sv, &cv);
        cs[k] = LOSS_AMP * cv;
        sn[k] = LOSS_AMP * sv;
    }
    for (int p = tid; p < SIZE * SIZE; p += BT) {
        const int r = p >> 6, c = p & 63;
        S[r][c] = make_float2(r == c ? 1.0f : 0.0f, 0.0f);
    }
    __syncthreads();

    for (int w = 2; w <= 188; ++w) {
        int i_min = (w + 3) / 3;
        if (i_min < 1) i_min = 1;
        int i_max = w >> 1;
        if (i_max > 63) i_max = 63;
        const int cnt = i_max - i_min + 1;

        for (int idx = warp; idx < cnt; idx += 32) {
            const int i = i_min + idx;
            const int j = w - 2 * i;
            const int k = ((i * (i - 1)) >> 1) + j;
            const float cc = cs[k], ss = sn[k];
            #pragma unroll
            for (int h = 0; h < 2; ++h) {
                const int c = lane + 32 * h;
                const float2 a = S[j][c];
                const float2 b = S[j + 1][c];
                const float nar = fmaf(cc, a.x, -(ss * b.y));
                const float nai = fmaf(cc, a.y,   ss * b.x);
                const float nbr = fmaf(cc, b.x, -(ss * a.y));
                const float nbi = fmaf(cc, b.y,   ss * a.x);
                S[j][c]     = make_float2(nar, nai);
                S[j + 1][c] = make_float2(nbr, nbi);
            }
        }
        __syncthreads();
    }

    // emit W[n'][k'] tf32-rounded in mma B-fragment order:
    //   n'<64: [ Ur | -Ui ] ; n'>=64: [ Ui | Ur ]
    //   n8t=n'>>3, g=n'&7, ks=k'>>3, t=k'&3, q=(k'>>2)&1, lane=g*4+t
    for (int p = tid; p < 128 * 128; p += BT) {
        const int n = p >> 7, k = p & 127;
        const float2 u = S[n & 63][k & 63];
        float v;
        if (n < 64) v = (k < 64) ? u.x : -u.y;
        else        v = (k < 64) ? u.y :  u.x;
        unsigned tv;
        asm("cvt.rna.tf32.f32 %0, %1;" : "=r"(tv) : "f"(v));
        const int n8t = n >> 3, g = n & 7;
        const int ks = k >> 3, t = k & 3, q = (k >> 2) & 1;
        g_Wfrag[(((n8t * 16 + ks) * 32 + g * 4 + t) << 1) + q] = tv;
    }
}

// ----------------------------- GEMM kernel --------------------------------
// 256 threads (8 warps: warpM 0..1 x warpN 0..3). Tile: 128 b x 128 n', K=128.
__global__ __launch_bounds__(256, 2)
void photonic_mma_kernel(const float* __restrict__ xr_g,
                         const float* __restrict__ xi_g,
                         float* __restrict__ out,
                         long long xsz, long long out_elems, int B) {
    extern __shared__ char smem[];
    unsigned* sxA = (unsigned*)smem;          // packed A: 8*16*32*4 u32 = 64 KB
    float* sre = (float*)smem;                // epilogue reuse: 128*66*4 B
    float* sim = (float*)(smem + 33792);      // 128*66*4 B

    const int tid  = threadIdx.x;
    const int lane = tid & 31;
    const int warp = tid >> 5;
    const int g = lane >> 2;                  // groupID 0..7
    const int t = lane & 3;                   // thread-in-group 0..3
    const int warpM = warp >> 2;              // 0..1
    const int warpN = warp & 3;               // 0..3

    const long long b0 = (long long)blockIdx.x * 128;
    if (b0 >= B) return;
    const long long base = b0 * SIZE;
    const long long xmax = xsz - 1;

    // ---- stage X = [xr | xi], tf32-rounded, in A-fragment order ----
    // element (row=batch, col=k'): m16t=row>>4, gg=row&7, half=(row>>3)&1,
    // ks=col>>3, tt=col&3, q=(col>>2)&1, r=half+2q
    // fidx = ((m16t*16+ks)*32 + gg*4+tt)*4 + r
    for (int p = tid; p < 128 * 64; p += 256) {
        const int bb = p >> 6, k = p & 63;
        long long gi = base + p;
        if (gi > xmax) gi = xmax;
        const float vr = xr_g[gi];
        const float vi = xi_g[gi];
        unsigned r_, i_;
        asm("cvt.rna.tf32.f32 %0, %1;" : "=r"(r_) : "f"(vr));
        asm("cvt.rna.tf32.f32 %0, %1;" : "=r"(i_) : "f"(vi));
        const int m16t = bb >> 4, gg = bb & 7, half = (bb >> 3) & 1;
        const int tt = k & 3, q = (k >> 2) & 1;
        const int bse = (m16t * 16) * 32 * 4 + (gg * 4 + tt) * 4 + half + 2 * q;
        // re at col=k (ks=k>>3), im at col=k+64 (ks=(k>>3)+8)
        sxA[bse + ((k >> 3)) * 128]     = r_;
        sxA[bse + ((k >> 3) + 8) * 128] = i_;
    }
    __syncthreads();

    // ---- accumulators ----
    float c[4][4][4];
    #pragma unroll
    for (int mt = 0; mt < 4; ++mt)
        #pragma unroll
        for (int nt = 0; nt < 4; ++nt)
            #pragma unroll
            for (int q = 0; q < 4; ++q) c[mt][nt][q] = 0.0f;

    #pragma unroll 4
    for (int ks = 0; ks < 16; ++ks) {
        uint4 a[4];
        #pragma unroll
        for (int mt = 0; mt < 4; ++mt)
            a[mt] = *(const uint4*)&sxA[(((warpM * 4 + mt) * 16 + ks) * 32
                                         + lane) * 4];
        uint2 bf[4];
        #pragma unroll
        for (int nt = 0; nt < 4; ++nt)
            bf[nt] = __ldg((const uint2*)&g_Wfrag[
                ((((warpN * 4 + nt) * 16 + ks) * 32 + lane) << 1)]);
        #pragma unroll
        for (int mt = 0; mt < 4; ++mt)
            #pragma unroll
            for (int nt = 0; nt < 4; ++nt)
                asm volatile(
                    "mma.sync.aligned.m16n8k8.row.col.f32.tf32.tf32.f32 "
                    "{%0,%1,%2,%3}, {%4,%5,%6,%7}, {%8,%9}, {%0,%1,%2,%3};"
                    : "+f"(c[mt][nt][0]), "+f"(c[mt][nt][1]),
                      "+f"(c[mt][nt][2]), "+f"(c[mt][nt][3])
                    : "r"(a[mt].x), "r"(a[mt].y), "r"(a[mt].z), "r"(a[mt].w),
                      "r"(bf[nt].x), "r"(bf[nt].y));
    }
    __syncthreads();   // X consumed; reuse smem for re/im planes

    // ---- scatter C fragments: n'<64 -> sre, n'>=64 -> sim ----
    #pragma unroll
    for (int mt = 0; mt < 4; ++mt) {
        const int row = warpM * 64 + mt * 16 + g;
        #pragma unroll
        for (int nt = 0; nt < 4; ++nt) {
            const int col = warpN * 32 + nt * 8 + 2 * t;
            float* dst = (col < 64) ? sre : sim;
            const int cc = col & 63;
            *(float2*)&dst[row * SP + cc] =
                make_float2(c[mt][nt][0], c[mt][nt][1]);
            *(float2*)&dst[(row + 8) * SP + cc] =
                make_float2(c[mt][nt][2], c[mt][nt][3]);
        }
    }
    __syncthreads();

    // ---- recombine + Kerr (cos=1, sin=ph in fp32), coalesced store ----
    for (int p = tid; p < 128 * 64; p += 256) {
        const int bb = p >> 6, n = p & 63;
        const float re = sre[bb * SP + n];
        const float im = sim[bb * SP + n];
        const float ph = KERR * fmaf(re, re, im * im);
        if (base + p < out_elems)
            out[base + p] = fmaf(-im, ph, re);
    }
}

// ------------------------------- launch ------------------------------------
extern "C" void kernel_launch(void* const* d_in, const int* in_sizes, int n_in,
                              void* d_out, int out_size) {
    if (n_in < 3) return;

    // phases = the input with the smallest element count (2016 vs B*64)
    int ph_idx = 0;
    for (int i = 1; i < 3; ++i)
        if (in_sizes[i] < in_sizes[ph_idx]) ph_idx = i;

    const float* xr = nullptr;
    const float* xi = nullptr;
    long long xsz = 0;
    for (int i = 0; i < 3; ++i) {
        if (i == ph_idx) continue;
        if (!xr) { xr = (const float*)d_in[i]; xsz = in_sizes[i]; }
        else     { xi = (const float*)d_in[i]; }
    }
    const float* phases = (const float*)d_in[ph_idx];
    const int nph = in_sizes[ph_idx];

    const int B = (int)(xsz / SIZE);
    const int nblocks = (B + 127) / 128;

    const int smem_bytes = 2 * 128 * SP * 4;   // 67,584 B (>= 64 KB packed A)
    cudaFuncSetAttribute(photonic_mma_kernel,
                         cudaFuncAttributeMaxDynamicSharedMemorySize,
                         smem_bytes);

    build_u_kernel<<<1, BT>>>(phases, nph);
    photonic_mma_kernel<<<nblocks, 256, smem_bytes>>>(
        xr, xi, (float*)d_out, xsz, (long long)out_size, B);
}

// round 11
// speedup vs baseline: 2.4108x; 1.2467x over previous
#include <cuda_runtime.h>

// ---------------------------------------------------------------------------
// PhotonicLayer via TF32 tensor cores (mma.sync.m16n8k8), fragment-packed.
// Real GEMM: X=[xr|xi] (Bx128), W=[[Ur,-Ui],[Ui,Ur]] (128x128), out'=X@W^T.
// A (X) staged in smem in fragment order -> LDS.128 per fragment.
// B (W) prepacked by build kernel in fragment order -> coalesced LDG.64.
// Warp n-tile pairing {n, n+64} -> re/im recombine + Kerr in registers,
// direct global stores (no epilogue smem roundtrip).
// ---------------------------------------------------------------------------

#define SIZE 64
#define NPH 2016
#define LOSS_AMP 0.9942600740f      // 10^(-0.05/20)
#define KERR 2.6e-17f               // NONLINEAR_COEFF * 1000
#define BT 672                      // build threads = 21 warps (widest wave)

// W in fragment order: flat idx = (((n8t*16 + ks)*32 + lane)*2 + q)
__device__ unsigned g_Wfrag[16 * 16 * 32 * 2];   // 64 KB

// ---------------------------- build kernel --------------------------------
// Wavefront schedule: rotation (i,j) at T = 2i+j; same-T rotations touch
// disjoint row pairs -> in-place, one barrier per wavefront. 21 warps cover
// the widest wavefront (21 rotations) in a single pass.
__global__ __launch_bounds__(BT)
void build_u_kernel(const float* __restrict__ phases, int nph) {
    __shared__ float2 S[SIZE][SIZE];    // [row][col] = U
    __shared__ float cs[NPH];
    __shared__ float sn[NPH];

    const int tid  = threadIdx.x;
    const int lane = tid & 31;
    const int warp = tid >> 5;
    const int pmax = (nph > 0) ? (nph - 1) : 0;

    for (int k = tid; k < NPH; k += BT) {
        const int kk = (k < pmax) ? k : pmax;
        float sv, cv;
        sincosf(phases[kk], &sv, &cv);
        cs[k] = LOSS_AMP * cv;
        sn[k] = LOSS_AMP * sv;
    }
    for (int p = tid; p < SIZE * SIZE; p += BT) {
        const int r = p >> 6, c = p & 63;
        S[r][c] = make_float2(r == c ? 1.0f : 0.0f, 0.0f);
    }
    __syncthreads();

    for (int w = 2; w <= 188; ++w) {
        int i_min = (w + 3) / 3;
        if (i_min < 1) i_min = 1;
        int i_max = w >> 1;
        if (i_max > 63) i_max = 63;
        const int cnt = i_max - i_min + 1;   // <= 21

        if (warp < cnt) {
            const int i = i_min + warp;
            const int j = w - 2 * i;
            const int k = ((i * (i - 1)) >> 1) + j;
            const float cc = cs[k], ss = sn[k];
            #pragma unroll
            for (int h = 0; h < 2; ++h) {
                const int c = lane + 32 * h;
                const float2 a = S[j][c];
                const float2 b = S[j + 1][c];
                const float nar = fmaf(cc, a.x, -(ss * b.y));
                const float nai = fmaf(cc, a.y,   ss * b.x);
                const float nbr = fmaf(cc, b.x, -(ss * a.y));
                const float nbi = fmaf(cc, b.y,   ss * a.x);
                S[j][c]     = make_float2(nar, nai);
                S[j + 1][c] = make_float2(nbr, nbi);
            }
        }
        __syncthreads();
    }

    // emit W[n'][k'] tf32-rounded in mma B-fragment order:
    //   n'<64: [ Ur | -Ui ] ; n'>=64: [ Ui | Ur ]
    for (int p = tid; p < 128 * 128; p += BT) {
        const int n = p >> 7, k = p & 127;
        const float2 u = S[n & 63][k & 63];
        float v;
        if (n < 64) v = (k < 64) ? u.x : -u.y;
        else        v = (k < 64) ? u.y :  u.x;
        unsigned tv;
        asm("cvt.rna.tf32.f32 %0, %1;" : "=r"(tv) : "f"(v));
        const int n8t = n >> 3, g = n & 7;
        const int ks = k >> 3, t = k & 3, q = (k >> 2) & 1;
        g_Wfrag[(((n8t * 16 + ks) * 32 + g * 4 + t) << 1) + q] = tv;
    }
}

// ----------------------------- GEMM kernel --------------------------------
// 256 threads (8 warps: warpM 0..1 x warpN 0..3). Tile: 128 b x 128 n', K=128.
// warpN owns n8-tiles {2w, 2w+1, 2w+8, 2w+9} so re/im of the same output
// column live in the same warp -> register epilogue.
__global__ __launch_bounds__(256, 2)
void photonic_mma_kernel(const float* __restrict__ xr_g,
                         const float* __restrict__ xi_g,
                         float* __restrict__ out,
                         long long xsz, long long out_elems, int B) {
    extern __shared__ char smem[];
    unsigned* sxA = (unsigned*)smem;          // packed A: 8*16*32*4 u32 = 64 KB

    const int tid  = threadIdx.x;
    const int lane = tid & 31;
    const int warp = tid >> 5;
    const int g = lane >> 2;                  // groupID 0..7
    const int t = lane & 3;                   // thread-in-group 0..3
    const int warpM = warp >> 2;              // 0..1
    const int warpN = warp & 3;               // 0..3

    const long long b0 = (long long)blockIdx.x * 128;
    if (b0 >= B) return;
    const long long base = b0 * SIZE;
    const long long xmax = xsz - 1;

    // ---- stage X = [xr | xi], tf32-rounded, in A-fragment order ----
    for (int p = tid; p < 128 * 64; p += 256) {
        const int bb = p >> 6, k = p & 63;
        long long gi = base + p;
        if (gi > xmax) gi = xmax;
        const float vr = xr_g[gi];
        const float vi = xi_g[gi];
        unsigned r_, i_;
        asm("cvt.rna.tf32.f32 %0, %1;" : "=r"(r_) : "f"(vr));
        asm("cvt.rna.tf32.f32 %0, %1;" : "=r"(i_) : "f"(vi));
        const int m16t = bb >> 4, gg = bb & 7, half = (bb >> 3) & 1;
        const int tt = k & 3, q = (k >> 2) & 1;
        const int bse = (m16t * 16) * 128 + (gg * 4 + tt) * 4 + half + 2 * q;
        sxA[bse + ((k >> 3)) * 128]     = r_;   // re: ks = k>>3
        sxA[bse + ((k >> 3) + 8) * 128] = i_;   // im: ks = k>>3 + 8
    }
    __syncthreads();

    // ---- accumulators: c[mt][cidx][4]; cidx 0,1 = re tiles, 2,3 = im ----
    float c[4][4][4];
    #pragma unroll
    for (int mt = 0; mt < 4; ++mt)
        #pragma unroll
        for (int nt = 0; nt < 4; ++nt)
            #pragma unroll
            for (int q = 0; q < 4; ++q) c[mt][nt][q] = 0.0f;

    // n8-tile ids for this warp: {2w, 2w+1, 2w+8, 2w+9}
    int n8tab[4];
    n8tab[0] = warpN * 2;     n8tab[1] = warpN * 2 + 1;
    n8tab[2] = warpN * 2 + 8; n8tab[3] = warpN * 2 + 9;

    #pragma unroll 4
    for (int ks = 0; ks < 16; ++ks) {
        uint4 a[4];
        #pragma unroll
        for (int mt = 0; mt < 4; ++mt)
            a[mt] = *(const uint4*)&sxA[(((warpM * 4 + mt) * 16 + ks) * 32
                                         + lane) * 4];
        uint2 bf[4];
        #pragma unroll
        for (int nt = 0; nt < 4; ++nt)
            bf[nt] = __ldg((const uint2*)&g_Wfrag[
                (((n8tab[nt] * 16 + ks) * 32 + lane) << 1)]);
        #pragma unroll
        for (int mt = 0; mt < 4; ++mt)
            #pragma unroll
            for (int nt = 0; nt < 4; ++nt)
                asm volatile(
                    "mma.sync.aligned.m16n8k8.row.col.f32.tf32.tf32.f32 "
                    "{%0,%1,%2,%3}, {%4,%5,%6,%7}, {%8,%9}, {%0,%1,%2,%3};"
                    : "+f"(c[mt][nt][0]), "+f"(c[mt][nt][1]),
                      "+f"(c[mt][nt][2]), "+f"(c[mt][nt][3])
                    : "r"(a[mt].x), "r"(a[mt].y), "r"(a[mt].z), "r"(a[mt].w),
                      "r"(bf[nt].x), "r"(bf[nt].y));
    }

    // ---- register epilogue: pair re (cidx) with im (cidx+2), Kerr, store ----
    #pragma unroll
    for (int mt = 0; mt < 4; ++mt) {
        const int row0 = warpM * 64 + mt * 16 + g;
        #pragma unroll
        for (int ci = 0; ci < 2; ++ci) {
            const int n = (warpN * 2 + ci) * 8 + 2 * t;
            #pragma unroll
            for (int h = 0; h < 2; ++h) {          // c0/c1 vs c2/c3 row halves
                const int row = row0 + 8 * h;
                const float re0 = c[mt][ci][2 * h];
                const float re1 = c[mt][ci][2 * h + 1];
                const float im0 = c[mt][ci + 2][2 * h];
                const float im1 = c[mt][ci + 2][2 * h + 1];
                const float ph0 = KERR * fmaf(re0, re0, im0 * im0);
                const float ph1 = KERR * fmaf(re1, re1, im1 * im1);
                const long long o = base + (long long)row * 64 + n;
                if (o + 2 <= out_elems)
                    *(float2*)&out[o] = make_float2(fmaf(-im0, ph0, re0),
                                                    fmaf(-im1, ph1, re1));
            }
        }
    }
}

// ------------------------------- launch ------------------------------------
extern "C" void kernel_launch(void* const* d_in, const int* in_sizes, int n_in,
                              void* d_out, int out_size) {
    if (n_in < 3) return;

    // phases = the input with the smallest element count (2016 vs B*64)
    int ph_idx = 0;
    for (int i = 1; i < 3; ++i)
        if (in_sizes[i] < in_sizes[ph_idx]) ph_idx = i;

    const float* xr = nullptr;
    const float* xi = nullptr;
    long long xsz = 0;
    for (int i = 0; i < 3; ++i) {
        if (i == ph_idx) continue;
        if (!xr) { xr = (const float*)d_in[i]; xsz = in_sizes[i]; }
        else     { xi = (const float*)d_in[i]; }
    }
    const float* phases = (const float*)d_in[ph_idx];
    const int nph = in_sizes[ph_idx];

    const int B = (int)(xsz / SIZE);
    const int nblocks = (B + 127) / 128;

    const int smem_bytes = 16 * 16 * 32 * 4 * sizeof(unsigned) / 4; // 65536
    cudaFuncSetAttribute(photonic_mma_kernel,
                         cudaFuncAttributeMaxDynamicSharedMemorySize,
                         65536);

    build_u_kernel<<<1, BT>>>(phases, nph);
    photonic_mma_kernel<<<nblocks, 256, 65536>>>(
        xr, xi, (float*)d_out, xsz, (long long)out_size, B);
    (void)smem_bytes;
}